// round 1
// baseline (speedup 1.0000x reference)
#include <cuda_runtime.h>

#define DD 128

// Scratch (static __device__ — no allocations allowed)
__device__ float g_p [4096 * DD];
__device__ float g_x2[4096];
__device__ float g_rx[4096];
__device__ float g_y2[65536];
__device__ float g_ry[65536];
__device__ float g_Wt[DD * DD];

__device__ __forceinline__ float wsum(float v) {
    #pragma unroll
    for (int o = 16; o > 0; o >>= 1) v += __shfl_xor_sync(0xffffffffu, v, o);
    return v;
}

// pack {x,x} into a 64-bit reg pair for f32x2 FMA
__device__ __forceinline__ unsigned long long dupf(float x) {
    unsigned int u = __float_as_uint(x);
    unsigned long long r;
    asm("mov.b64 %0, {%1, %1};" : "=l"(r) : "r"(u));
    return r;
}

// packed fp32x2 FMA (Blackwell FFMA2): d.lo += a.lo*b.lo ; d.hi += a.hi*b.hi
__device__ __forceinline__ void ffma2(unsigned long long& d,
                                      unsigned long long a,
                                      unsigned long long b) {
    asm("fma.rn.f32x2 %0, %1, %2, %0;" : "+l"(d) : "l"(a), "l"(b));
}

__device__ __forceinline__ float2 unpk(unsigned long long v) {
    unsigned int lo, hi;
    asm("mov.b64 {%0, %1}, %2;" : "=r"(lo), "=r"(hi) : "l"(v));
    return make_float2(__uint_as_float(lo), __uint_as_float(hi));
}

// ---------------- kernel 1: transpose W into g_Wt (g_Wt[e][d] = W[d][e]) ----
__global__ void hd_transpose_W(const float* __restrict__ W) {
    int idx = blockIdx.x * blockDim.x + threadIdx.x;
    if (idx < DD * DD) {
        int d = idx >> 7, e = idx & (DD - 1);
        g_Wt[e * DD + d] = W[idx];
    }
}

// ---------------- kernel 2: per-code stats: y2, 1/(1-y2) ---------------------
__global__ void hd_prep_codes(const float* __restrict__ Y, int K) {
    int lane = threadIdx.x & 31;
    int k = blockIdx.x * (blockDim.x >> 5) + (threadIdx.x >> 5);
    if (k >= K) return;
    const float* y = Y + (size_t)k * DD;
    float s = 0.f;
    #pragma unroll
    for (int q = 0; q < 4; q++) { float t = y[lane + 32 * q]; s = fmaf(t, t, s); }
    s = wsum(s);
    if (lane == 0) {
        g_y2[k] = s;
        g_ry[k] = 1.f / fmaxf(1.f - s, 1e-12f);
    }
}

// ---------------- kernel 3: hyperbolic MLP, warp-per-row ---------------------
// p = mobius_add(mobius_matvec(W, expmap0(v)), expmap0(b))
// (reference's logmap0->expmap0 round-trip is the identity; skipped)
__global__ void hd_prep_rows(const float* __restrict__ V,
                             const float* __restrict__ bvec, int N) {
    int lane = threadIdx.x & 31;
    int row = blockIdx.x * (blockDim.x >> 5) + (threadIdx.x >> 5);
    if (row >= N) return;
    const float* v = V + (size_t)row * DD;

    // expmap0(v)
    float vq[4];
    #pragma unroll
    for (int q = 0; q < 4; q++) vq[q] = v[lane + 32 * q];
    float n2 = wsum(vq[0]*vq[0] + vq[1]*vq[1] + vq[2]*vq[2] + vq[3]*vq[3]);
    float n  = sqrtf(fmaxf(n2, 1e-30f));
    float xn = tanhf(n);              // == |p0|
    float s0 = xn / n;
    float p0[4];
    #pragma unroll
    for (int q = 0; q < 4; q++) p0[q] = s0 * vq[q];

    // Mx = W @ p0  (thread owns dims d = lane + 32q; g_Wt[e][d] conflict-free)
    float mq[4] = {0.f, 0.f, 0.f, 0.f};
    #pragma unroll
    for (int e = 0; e < DD; e++) {
        float pe = __shfl_sync(0xffffffffu, p0[e >> 5], e & 31);
        #pragma unroll
        for (int q = 0; q < 4; q++)
            mq[q] = fmaf(pe, g_Wt[e * DD + 32 * q + lane], mq[q]);
    }
    float mxn2 = wsum(mq[0]*mq[0] + mq[1]*mq[1] + mq[2]*mq[2] + mq[3]*mq[3]);
    float mxn  = sqrtf(fmaxf(mxn2, 1e-30f));
    float xc   = fminf(xn, 1.f - 1e-5f);
    float ath  = 0.5f * __logf((1.f + xc) / (1.f - xc));   // artanh(xn)
    float g    = tanhf(mxn / fmaxf(xn, 1e-15f) * ath) / mxn;
    float rq[4];
    #pragma unroll
    for (int q = 0; q < 4; q++) rq[q] = g * mq[q];

    // eb = expmap0(b)
    float bq[4];
    #pragma unroll
    for (int q = 0; q < 4; q++) bq[q] = bvec[lane + 32 * q];
    float bn2 = wsum(bq[0]*bq[0] + bq[1]*bq[1] + bq[2]*bq[2] + bq[3]*bq[3]);
    float bn  = sqrtf(fmaxf(bn2, 1e-30f));
    float tb  = tanhf(bn);
    float sb  = tb / bn;
    float ebq[4];
    #pragma unroll
    for (int q = 0; q < 4; q++) ebq[q] = sb * bq[q];
    float y2 = tb * tb;

    // mobius_add(r, eb)
    float x2 = wsum(rq[0]*rq[0] + rq[1]*rq[1] + rq[2]*rq[2] + rq[3]*rq[3]);
    float xy = wsum(rq[0]*ebq[0] + rq[1]*ebq[1] + rq[2]*ebq[2] + rq[3]*ebq[3]);
    float ca  = 1.f + 2.f * xy + y2;
    float cb  = 1.f - x2;
    float den = fmaxf(1.f + 2.f * xy + x2 * y2, 1e-15f);
    float inv = 1.f / den;
    float pq[4], ps = 0.f;
    #pragma unroll
    for (int q = 0; q < 4; q++) {
        pq[q] = (ca * rq[q] + cb * ebq[q]) * inv;
        ps = fmaf(pq[q], pq[q], ps);
    }
    float px2 = wsum(ps);
    float* Pr = g_p + (size_t)row * DD;
    #pragma unroll
    for (int q = 0; q < 4; q++) Pr[lane + 32 * q] = pq[q];
    if (lane == 0) {
        g_x2[row] = px2;
        g_rx[row] = 2.f / fmaxf(1.f - px2, 1e-12f);
    }
}

// ---------------- kernel 4: fused GEMM + hyperbolic-distance epilogue --------
// logits[n,k] = -acosh(1 + 2|x-y|^2/((1-x2)(1-y2)))^2 / T^2 + fb[k]
#define BM 128
#define BN 128
#define BKC 32

__global__ __launch_bounds__(256, 2)
void hd_gemm_epi(const float* __restrict__ Y, const float* __restrict__ fb,
                 const float* __restrict__ temp, float* __restrict__ out, int K) {
    __shared__ __align__(16) float As[BKC][BM];   // As[d][m]
    __shared__ __align__(16) float Bs[BKC][BN];   // Bs[d][n]
    const int tid = threadIdx.x;
    const int tn = tid & 15, tm = tid >> 4;       // 16x16 thread grid, 8x8 micro-tile
    const int c0 = blockIdx.x * BN, m0 = blockIdx.y * BM;

    unsigned long long acc[8][4];                 // acc[i][jp] = (xy[i][2jp], xy[i][2jp+1])
    #pragma unroll
    for (int i = 0; i < 8; i++)
        #pragma unroll
        for (int j = 0; j < 4; j++) acc[i][j] = 0ULL;

    for (int d0 = 0; d0 < DD; d0 += BKC) {
        __syncthreads();
        #pragma unroll
        for (int i = 0; i < 4; i++) {
            int f = tid + 256 * i;                // 1024 float4 per tile
            int m = f >> 3, d4 = f & 7;
            float4 av = *(const float4*)(g_p + (size_t)(m0 + m) * DD + d0 + 4 * d4);
            As[4*d4+0][m] = av.x; As[4*d4+1][m] = av.y;
            As[4*d4+2][m] = av.z; As[4*d4+3][m] = av.w;
            float4 bv = *(const float4*)(Y + (size_t)(c0 + m) * DD + d0 + 4 * d4);
            Bs[4*d4+0][m] = bv.x; Bs[4*d4+1][m] = bv.y;
            Bs[4*d4+2][m] = bv.z; Bs[4*d4+3][m] = bv.w;
        }
        __syncthreads();
        #pragma unroll 8
        for (int d = 0; d < BKC; d++) {
            float4 a0 = *(const float4*)&As[d][tm * 8];
            float4 a1 = *(const float4*)&As[d][tm * 8 + 4];
            ulonglong2 u0 = *(const ulonglong2*)&Bs[d][tn * 8];
            ulonglong2 u1 = *(const ulonglong2*)&Bs[d][tn * 8 + 4];
            unsigned long long ad[8];
            ad[0] = dupf(a0.x); ad[1] = dupf(a0.y); ad[2] = dupf(a0.z); ad[3] = dupf(a0.w);
            ad[4] = dupf(a1.x); ad[5] = dupf(a1.y); ad[6] = dupf(a1.z); ad[7] = dupf(a1.w);
            unsigned long long bb[4] = {u0.x, u0.y, u1.x, u1.y};
            #pragma unroll
            for (int i = 0; i < 8; i++)
                #pragma unroll
                for (int jp = 0; jp < 4; jp++)
                    ffma2(acc[i][jp], ad[i], bb[jp]);
        }
    }

    float x2r[8], rxr[8], y2c[8], ryc[8], fbc[8];
    #pragma unroll
    for (int i = 0; i < 8; i++) {
        int r = m0 + tm * 8 + i;
        x2r[i] = g_x2[r]; rxr[i] = g_rx[r];
    }
    #pragma unroll
    for (int j = 0; j < 8; j++) {
        int c = c0 + tn * 8 + j;
        y2c[j] = g_y2[c]; ryc[j] = g_ry[c]; fbc[j] = __ldg(fb + c);
    }
    float T = __ldg(temp);
    float nit2 = -1.f / (T * T);

    #pragma unroll
    for (int i = 0; i < 8; i++) {
        float res[8];
        #pragma unroll
        for (int jp = 0; jp < 4; jp++) {
            float2 xy2 = unpk(acc[i][jp]);
            float xv0 = xy2.x, xv1 = xy2.y;
            #pragma unroll
            for (int h = 0; h < 2; h++) {
                int j = 2 * jp + h;
                float xv = h ? xv1 : xv0;
                float u = fmaf(-2.f, xv, x2r[i] + y2c[j]);   // |x-y|^2
                u = fmaxf(u, 0.f);
                float zm1 = u * (rxr[i] * ryc[j]);           // cosh(d) - 1
                float w = sqrtf(fmaf(zm1, zm1, 2.f * zm1));  // sqrt(z^2-1)
                float l = __logf(1.f + zm1 + w);             // acosh(z) = d
                res[j] = fmaf(l * l, nit2, fbc[j]);
            }
        }
        size_t o = (size_t)(m0 + tm * 8 + i) * K + c0 + tn * 8;
        *(float4*)(out + o)     = make_float4(res[0], res[1], res[2], res[3]);
        *(float4*)(out + o + 4) = make_float4(res[4], res[5], res[6], res[7]);
    }
}

extern "C" void kernel_launch(void* const* d_in, const int* in_sizes, int n_in,
                              void* d_out, int out_size) {
    const float* v     = (const float*)d_in[0];  // [B,S,D]
    const float* codes = (const float*)d_in[1];  // [K,D]
    const float* W     = (const float*)d_in[2];  // [D,D]
    const float* b     = (const float*)d_in[3];  // [D]
    const float* fb    = (const float*)d_in[4];  // [K]
    const float* temp  = (const float*)d_in[5];  // scalar

    const int D = in_sizes[3];            // 128
    const int N = in_sizes[0] / D;        // 2048
    const int K = in_sizes[4];            // 32000

    hd_transpose_W<<<(D * D + 255) / 256, 256>>>(W);
    hd_prep_codes<<<(K + 7) / 8, 256>>>(codes, K);
    hd_prep_rows<<<(N + 7) / 8, 256>>>(v, b, N);

    dim3 grid(K / BN, N / BM);
    hd_gemm_epi<<<grid, 256>>>(codes, fb, temp, (float*)d_out, K);
}

// round 3
// speedup vs baseline: 3.1631x; 3.1631x over previous
#include <cuda_runtime.h>
#include <cuda_bf16.h>
#include <cstdint>

#define DD 128

#if defined(__CUDA_ARCH__) && defined(__CUDA_ARCH_FEAT_SM103_ALL)
#define TC_OK 1
#else
#define TC_OK 0
#endif

// -------------------- device scratch (no allocations allowed) ---------------
__device__ float g_x2[4096];
__device__ float g_rx[4096];
__device__ float g_y2[65536];
__device__ float g_ry[65536];
__device__ float g_Wt[DD * DD];
__device__ __nv_bfloat16 g_phi[4096 * DD];
__device__ __nv_bfloat16 g_plo[4096 * DD];
__device__ __nv_bfloat16 g_yhi[32768 * DD];
__device__ __nv_bfloat16 g_ylo[32768 * DD];

// -------------------- small helpers ----------------------------------------
__device__ __forceinline__ float wsum(float v) {
    #pragma unroll
    for (int o = 16; o > 0; o >>= 1) v += __shfl_xor_sync(0xffffffffu, v, o);
    return v;
}

__device__ __forceinline__ uint32_t s2u(const void* p) {
    uint32_t a;
    asm("{ .reg .u64 t; cvta.to.shared.u64 t, %1; cvt.u32.u64 %0, t; }"
        : "=r"(a) : "l"(p));
    return a;
}

__device__ __forceinline__ void cpasync16(uint32_t dst, const void* src) {
    asm volatile("cp.async.cg.shared.global [%0], [%1], 16;" :: "r"(dst), "l"(src));
}
__device__ __forceinline__ void cp_commit() { asm volatile("cp.async.commit_group;"); }
__device__ __forceinline__ void cp_wait0()  { asm volatile("cp.async.wait_group 0;" ::: "memory"); }
__device__ __forceinline__ void cp_wait1()  { asm volatile("cp.async.wait_group 1;" ::: "memory"); }

__device__ __forceinline__ void mbar_init(uint32_t a, uint32_t cnt) {
    asm volatile("mbarrier.init.shared.b64 [%0], %1;" :: "r"(a), "r"(cnt) : "memory");
}
__device__ __forceinline__ void mbar_wait(uint32_t a, uint32_t parity) {
    asm volatile(
        "{\n\t.reg .pred P;\n"
        "W%=:\n\t"
        "mbarrier.try_wait.parity.acquire.cta.shared::cta.b64 P, [%0], %1;\n\t"
        "@!P bra W%=;\n\t}"
        :: "r"(a), "r"(parity) : "memory");
}

#if TC_OK
__device__ __forceinline__ void tm_alloc(uint32_t smem_res, uint32_t ncols) {
    asm volatile("tcgen05.alloc.cta_group::1.sync.aligned.shared::cta.b32 [%0], %1;"
                 :: "r"(smem_res), "r"(ncols) : "memory");
}
__device__ __forceinline__ void tm_dealloc(uint32_t tmem, uint32_t ncols) {
    asm volatile("tcgen05.dealloc.cta_group::1.sync.aligned.b32 %0, %1;" :: "r"(tmem), "r"(ncols));
}
__device__ __forceinline__ void tm_commit(uint32_t mbar) {
    asm volatile("tcgen05.commit.cta_group::1.mbarrier::arrive::one.shared::cluster.b64 [%0];"
                 :: "r"(mbar) : "memory");
}
__device__ __forceinline__ void tm_fence_after() {
    asm volatile("tcgen05.fence::after_thread_sync;" ::: "memory");
}
__device__ __forceinline__ void fence_async_shared() {
    asm volatile("fence.proxy.async.shared::cta;" ::: "memory");
}
__device__ __forceinline__ void tm_waitld() {
    asm volatile("tcgen05.wait::ld.sync.aligned;" ::: "memory");
}
__device__ __forceinline__ void ldtm16(uint32_t* r, uint32_t a) {
    asm volatile("tcgen05.ld.sync.aligned.32x32b.x16.b32 "
                 "{%0,%1,%2,%3,%4,%5,%6,%7,%8,%9,%10,%11,%12,%13,%14,%15}, [%16];"
                 : "=r"(r[0]), "=r"(r[1]), "=r"(r[2]),  "=r"(r[3]),
                   "=r"(r[4]), "=r"(r[5]), "=r"(r[6]),  "=r"(r[7]),
                   "=r"(r[8]), "=r"(r[9]), "=r"(r[10]), "=r"(r[11]),
                   "=r"(r[12]), "=r"(r[13]), "=r"(r[14]), "=r"(r[15])
                 : "r"(a));
}

// SS bf16 MMA, cg1, fp32 accumulate.
#define IDESC_BF16_128x128 ((1u<<4)|(1u<<7)|(1u<<10)|((128u/8u)<<17)|((128u/16u)<<24))

__device__ __forceinline__ void mma_ss(uint32_t d, uint64_t a, uint64_t b,
                                       uint32_t en) {
    asm volatile(
        "{\n\t.reg .pred p;\n\t"
        "setp.ne.u32 p, %5, 0;\n\t"
        "tcgen05.mma.cta_group::1.kind::f16 [%0], %1, %2, %3, {%4, %4, %4, %4}, p;\n\t}"
        :: "r"(d), "l"(a), "l"(b), "r"(IDESC_BF16_128x128), "r"(0u), "r"(en)
        : "memory");
}
#endif  // TC_OK

// 64-bit SMEM descriptor: SW128, version 1 (Blackwell), SBO=64, LBO=1
__device__ __forceinline__ uint64_t mkdesc(uint32_t addr) {
    return ((uint64_t)2 << 61) | ((uint64_t)1 << 46) | ((uint64_t)64 << 32)
         | ((uint64_t)1 << 16) | (uint64_t)((addr >> 4) & 0x3FFFu);
}

// Atom-blocked SW128 offset for a 128-row x 128-col bf16 tile.
// atom = 8 rows x 64 bf16 (1024B). 16 atom-rows x 2 atom-cols, strides (1,16).
__device__ __forceinline__ uint32_t tile_off(int r, int g) {
    uint32_t lin = (uint32_t)((r >> 3) + ((g >> 3) << 4)) * 1024u
                 + (uint32_t)(r & 7) * 128u + (uint32_t)(g & 7) * 16u;
    return lin ^ ((lin >> 3) & 0x70u);
}

// -------------------- kernel 1: transpose W --------------------------------
__global__ void hd_transpose_W(const float* __restrict__ W) {
    int idx = blockIdx.x * blockDim.x + threadIdx.x;
    if (idx < DD * DD) {
        int d = idx >> 7, e = idx & (DD - 1);
        g_Wt[e * DD + d] = W[idx];
    }
}

// -------------------- kernel 2: per-code stats + bf16 split -----------------
__global__ void hd_prep_codes(const float* __restrict__ Y, int K) {
    int lane = threadIdx.x & 31;
    int k = blockIdx.x * (blockDim.x >> 5) + (threadIdx.x >> 5);
    if (k >= K) return;
    const float* y = Y + (size_t)k * DD;
    float s = 0.f;
    #pragma unroll
    for (int q = 0; q < 4; q++) {
        int d = lane + 32 * q;
        float t = y[d];
        s = fmaf(t, t, s);
        __nv_bfloat16 hi = __float2bfloat16_rn(t);
        __nv_bfloat16 lo = __float2bfloat16_rn(t - __bfloat162float(hi));
        g_yhi[(size_t)k * DD + d] = hi;
        g_ylo[(size_t)k * DD + d] = lo;
    }
    s = wsum(s);
    if (lane == 0) {
        g_y2[k] = s;
        g_ry[k] = 1.f / fmaxf(1.f - s, 1e-12f);
    }
}

// -------------------- kernel 3: hyperbolic MLP, warp-per-row ----------------
__global__ void hd_prep_rows(const float* __restrict__ V,
                             const float* __restrict__ bvec, int N) {
    int lane = threadIdx.x & 31;
    int row = blockIdx.x * (blockDim.x >> 5) + (threadIdx.x >> 5);
    if (row >= N) return;
    const float* v = V + (size_t)row * DD;

    float vq[4];
    #pragma unroll
    for (int q = 0; q < 4; q++) vq[q] = v[lane + 32 * q];
    float n2 = wsum(vq[0]*vq[0] + vq[1]*vq[1] + vq[2]*vq[2] + vq[3]*vq[3]);
    float n  = sqrtf(fmaxf(n2, 1e-30f));
    float xn = tanhf(n);
    float s0 = xn / n;
    float p0[4];
    #pragma unroll
    for (int q = 0; q < 4; q++) p0[q] = s0 * vq[q];

    float mq[4] = {0.f, 0.f, 0.f, 0.f};
    #pragma unroll
    for (int e = 0; e < DD; e++) {
        float pe = __shfl_sync(0xffffffffu, p0[e >> 5], e & 31);
        #pragma unroll
        for (int q = 0; q < 4; q++)
            mq[q] = fmaf(pe, g_Wt[e * DD + 32 * q + lane], mq[q]);
    }
    float mxn2 = wsum(mq[0]*mq[0] + mq[1]*mq[1] + mq[2]*mq[2] + mq[3]*mq[3]);
    float mxn  = sqrtf(fmaxf(mxn2, 1e-30f));
    float xc   = fminf(xn, 1.f - 1e-5f);
    float ath  = 0.5f * __logf((1.f + xc) / (1.f - xc));
    float g    = tanhf(mxn / fmaxf(xn, 1e-15f) * ath) / mxn;
    float rq[4];
    #pragma unroll
    for (int q = 0; q < 4; q++) rq[q] = g * mq[q];

    float bq[4];
    #pragma unroll
    for (int q = 0; q < 4; q++) bq[q] = bvec[lane + 32 * q];
    float bn2 = wsum(bq[0]*bq[0] + bq[1]*bq[1] + bq[2]*bq[2] + bq[3]*bq[3]);
    float bn  = sqrtf(fmaxf(bn2, 1e-30f));
    float tb  = tanhf(bn);
    float sb  = tb / bn;
    float ebq[4];
    #pragma unroll
    for (int q = 0; q < 4; q++) ebq[q] = sb * bq[q];
    float y2 = tb * tb;

    float x2 = wsum(rq[0]*rq[0] + rq[1]*rq[1] + rq[2]*rq[2] + rq[3]*rq[3]);
    float xy = wsum(rq[0]*ebq[0] + rq[1]*ebq[1] + rq[2]*ebq[2] + rq[3]*ebq[3]);
    float ca  = 1.f + 2.f * xy + y2;
    float cb  = 1.f - x2;
    float den = fmaxf(1.f + 2.f * xy + x2 * y2, 1e-15f);
    float inv = 1.f / den;
    float pq[4], ps = 0.f;
    #pragma unroll
    for (int q = 0; q < 4; q++) {
        pq[q] = (ca * rq[q] + cb * ebq[q]) * inv;
        ps = fmaf(pq[q], pq[q], ps);
    }
    float px2 = wsum(ps);
    #pragma unroll
    for (int q = 0; q < 4; q++) {
        int d = lane + 32 * q;
        __nv_bfloat16 hi = __float2bfloat16_rn(pq[q]);
        __nv_bfloat16 lo = __float2bfloat16_rn(pq[q] - __bfloat162float(hi));
        g_phi[(size_t)row * DD + d] = hi;
        g_plo[(size_t)row * DD + d] = lo;
    }
    if (lane == 0) {
        g_x2[row] = px2;
        g_rx[row] = 2.f / fmaxf(1.f - px2, 1e-12f);
    }
}

// -------------------- kernel 4: tcgen05 GEMM + fused epilogue ---------------
#define SM_TMEMPTR 0
#define SM_MBAR    8
#define SM_A       1024
#define SM_B       (SM_A + 65536)
#define SM_STG     (SM_B + 131072)
#define SM_TOTAL   (SM_STG + 8 * 16 * 33 * 4)

__device__ __forceinline__ void fill_tile(uint32_t dst_base,
                                          const __nv_bfloat16* __restrict__ hi,
                                          const __nv_bfloat16* __restrict__ lo,
                                          int row0, int tid) {
    #pragma unroll
    for (int k = 0; k < 16; k++) {
        int idx = tid + 256 * k;
        int s = idx >> 11, f = idx & 2047;
        int r = f >> 4, g = f & 15;
        const __nv_bfloat16* src = (s ? lo : hi) + ((size_t)(row0 + r) * DD + g * 8);
        cpasync16(dst_base + (uint32_t)s * 32768u + tile_off(r, g), src);
    }
}

#if TC_OK
__device__ __forceinline__ void issue_tile(uint32_t sa, uint32_t sbuf, uint32_t d) {
    uint64_t ah = mkdesc(sa), al = mkdesc(sa + 32768u);
    uint64_t bh = mkdesc(sbuf), bl = mkdesc(sbuf + 32768u);
    #pragma unroll
    for (int kk = 0; kk < 8; kk++) {
        uint32_t off = (uint32_t)(kk >> 2) * 1024u + (uint32_t)(kk & 3) * 2u;
        mma_ss(d, ah + off, bh + off, kk > 0 ? 1u : 0u);
        mma_ss(d, ah + off, bl + off, 1u);
        mma_ss(d, al + off, bh + off, 1u);
    }
}
#endif

__device__ __forceinline__ float hd_logit(float xv, float x2r, float rxr,
                                          float y2c, float ryc, float fbc,
                                          float nit2) {
    float u = fmaf(-2.f, xv, x2r + y2c);
    u = fmaxf(u, 0.f);
    float zm1 = u * (rxr * ryc);
    float a = fmaxf(fmaf(zm1, zm1, 2.f * zm1), 1e-30f);
    float wq = a * rsqrtf(a);
    float l = __logf(1.f + zm1 + wq);
    return fmaf(l * l, nit2, fbc);
}

__global__ void __launch_bounds__(256, 1)
hd_gemm_tc(const float* __restrict__ fb, const float* __restrict__ temp,
           float* __restrict__ out, int NROW, int K) {
    extern __shared__ char smem[];
    uint32_t sb = s2u(smem);
    int tid = threadIdx.x, w = tid >> 5, lane = tid & 31;

    const int NT = K >> 7;
    const int total = (NROW >> 7) * NT;
    const int per = (total + gridDim.x - 1) / gridDim.x;
    int t = blockIdx.x * per;
    const int tend = min(total, t + per);

    const float T = __ldg(temp);
    const float nit2 = -1.f / (T * T);

#if TC_OK
    if (w == 0) tm_alloc(sb + SM_TMEMPTR, 256);
    if (tid == 0) mbar_init(sb + SM_MBAR, 1);
    __syncthreads();
    uint32_t tbase;
    asm volatile("ld.shared.b32 %0, [%1];" : "=r"(tbase) : "r"(sb + SM_TMEMPTR));

    float* stgf = (float*)(smem + SM_STG) + w * (16 * 33);
    uint32_t ph = 0;
    while (t < tend) {
        const int m = t / NT;
        const int segend = min(tend, (m + 1) * NT);

        fill_tile(sb + SM_A, g_phi, g_plo, m << 7, tid);
        fill_tile(sb + SM_B + (uint32_t)(t & 1) * 65536u, g_yhi, g_ylo,
                  (t % NT) << 7, tid);
        cp_commit();
        if (t + 1 < segend) {
            fill_tile(sb + SM_B + (uint32_t)((t + 1) & 1) * 65536u, g_yhi, g_ylo,
                      ((t + 1) % NT) << 7, tid);
            cp_commit();
            cp_wait1();
        } else {
            cp_wait0();
        }
        __syncthreads();
        if (tid == 0) {
            fence_async_shared();
            issue_tile(sb + SM_A, sb + SM_B + (uint32_t)(t & 1) * 65536u,
                       tbase + (uint32_t)(t & 1) * 128u);
            tm_commit(sb + SM_MBAR);
        }

        const int rowl = ((w & 3) << 5) + lane;
        const int grow = (m << 7) + rowl;
        const float x2r = g_x2[grow], rxr = g_rx[grow];

        for (int i = t; i < segend; i++) {
            mbar_wait(sb + SM_MBAR, ph);
            ph ^= 1;
            if (i + 1 < segend) {
                cp_wait0();
                __syncthreads();
                if (tid == 0) {
                    fence_async_shared();
                    issue_tile(sb + SM_A,
                               sb + SM_B + (uint32_t)((i + 1) & 1) * 65536u,
                               tbase + (uint32_t)((i + 1) & 1) * 128u);
                    tm_commit(sb + SM_MBAR);
                }
                if (i + 2 < segend) {
                    fill_tile(sb + SM_B + (uint32_t)(i & 1) * 65536u,
                              g_yhi, g_ylo, ((i + 2) % NT) << 7, tid);
                    cp_commit();
                }
            }
            tm_fence_after();
            const uint32_t dbase = tbase + (uint32_t)(i & 1) * 128u + ((w >> 2) << 6);
            const int n = i % NT;
            const int colbase = (n << 7) + ((w >> 2) << 6);
            #pragma unroll
            for (int ch = 0; ch < 4; ch++) {
                uint32_t r[16];
                ldtm16(r, dbase + (uint32_t)ch * 16u);
                tm_waitld();
                float res[16];
                #pragma unroll
                for (int j = 0; j < 16; j++) {
                    const int c = colbase + ch * 16 + j;
                    res[j] = hd_logit(__uint_as_float(r[j]), x2r, rxr,
                                      __ldg(&g_y2[c]), __ldg(&g_ry[c]),
                                      __ldg(&fb[c]), nit2);
                }
                #pragma unroll
                for (int j = 0; j < 16; j++)
                    stgf[j * 33 + lane] = res[j];
                __syncwarp();
                #pragma unroll
                for (int it = 0; it < 4; it++) {
                    int rr = it * 8 + (lane >> 2);
                    int cc = (lane & 3) << 2;
                    float4 v;
                    v.x = stgf[(cc + 0) * 33 + rr];
                    v.y = stgf[(cc + 1) * 33 + rr];
                    v.z = stgf[(cc + 2) * 33 + rr];
                    v.w = stgf[(cc + 3) * 33 + rr];
                    int orow = (m << 7) + ((w & 3) << 5) + rr;
                    *(float4*)(out + (size_t)orow * K + colbase + ch * 16 + cc) = v;
                }
                __syncwarp();
            }
        }
        t = segend;
    }
    __syncthreads();
    if (w == 0) tm_dealloc(tbase, 256);
#else
    // -------- fallback (plain sm_103 cubin; GB300 loads the sm_103a one) ----
    float* Af = (float*)(smem);            // Af[d][m], 64KB
    float* Bf = (float*)(smem + 65536);    // Bf[d][n], 64KB
    const int tn = tid & 15, tm = tid >> 4;
    int cur_m = -1;
    while (t < tend) {
        const int m = t / NT, n = t % NT;
        __syncthreads();
        if (m != cur_m) {
            for (int idx = tid; idx < 128 * 128; idx += 256) {
                int r = idx >> 7, d = idx & 127;
                size_t o = (size_t)((m << 7) + r) * DD + d;
                Af[d * 128 + r] = __bfloat162float(g_phi[o]) + __bfloat162float(g_plo[o]);
            }
            cur_m = m;
        }
        for (int idx = tid; idx < 128 * 128; idx += 256) {
            int r = idx >> 7, d = idx & 127;
            size_t o = (size_t)((n << 7) + r) * DD + d;
            Bf[d * 128 + r] = __bfloat162float(g_yhi[o]) + __bfloat162float(g_ylo[o]);
        }
        __syncthreads();
        float acc[8][8];
        #pragma unroll
        for (int i = 0; i < 8; i++)
            #pragma unroll
            for (int j = 0; j < 8; j++) acc[i][j] = 0.f;
        for (int d = 0; d < 128; d++) {
            float av[8], bv[8];
            #pragma unroll
            for (int i = 0; i < 8; i++) av[i] = Af[d * 128 + tm * 8 + i];
            #pragma unroll
            for (int j = 0; j < 8; j++) bv[j] = Bf[d * 128 + tn * 8 + j];
            #pragma unroll
            for (int i = 0; i < 8; i++)
                #pragma unroll
                for (int j = 0; j < 8; j++) acc[i][j] = fmaf(av[i], bv[j], acc[i][j]);
        }
        #pragma unroll
        for (int i = 0; i < 8; i++) {
            int grow = (m << 7) + tm * 8 + i;
            float x2r = g_x2[grow], rxr = g_rx[grow];
            #pragma unroll
            for (int j = 0; j < 8; j++) {
                int c = (n << 7) + tn * 8 + j;
                out[(size_t)grow * K + c] =
                    hd_logit(acc[i][j], x2r, rxr, g_y2[c], g_ry[c], fb[c], nit2);
            }
        }
        t++;
    }
#endif
}

// -------------------- launch -------------------------------------------------
extern "C" void kernel_launch(void* const* d_in, const int* in_sizes, int n_in,
                              void* d_out, int out_size) {
    const float* v     = (const float*)d_in[0];
    const float* codes = (const float*)d_in[1];
    const float* W     = (const float*)d_in[2];
    const float* b     = (const float*)d_in[3];
    const float* fb    = (const float*)d_in[4];
    const float* temp  = (const float*)d_in[5];

    const int D = in_sizes[3];            // 128
    const int N = in_sizes[0] / D;        // 2048
    const int K = in_sizes[4];            // 32000

    cudaFuncSetAttribute(hd_gemm_tc, cudaFuncAttributeMaxDynamicSharedMemorySize,
                         SM_TOTAL);

    hd_transpose_W<<<(D * D + 255) / 256, 256>>>(W);
    hd_prep_codes<<<(K + 7) / 8, 256>>>(codes, K);
    hd_prep_rows<<<(N + 7) / 8, 256>>>(v, b, N);
    hd_gemm_tc<<<148, 256, SM_TOTAL>>>(fb, temp, (float*)d_out, N, K);
}

// round 4
// speedup vs baseline: 3.2917x; 1.0407x over previous
#include <cuda_runtime.h>
#include <cuda_bf16.h>
#include <cstdint>

#define DD 128

#if defined(__CUDA_ARCH__) && defined(__CUDA_ARCH_FEAT_SM103_ALL)
#define TC_OK 1
#else
#define TC_OK 0
#endif

// -------------------- device scratch (no allocations allowed) ---------------
__device__ float g_x2[4096];
__device__ float g_rx[4096];
__device__ float4 g_cc[32768];            // per-code {y2, 1/(1-y2), fb, 0}
__device__ float g_Wt[DD * DD];
__device__ __nv_bfloat16 g_phi[4096 * DD];
__device__ __nv_bfloat16 g_plo[4096 * DD];
__device__ __nv_bfloat16 g_yhi[32768 * DD];
__device__ __nv_bfloat16 g_ylo[32768 * DD];

// -------------------- small helpers ----------------------------------------
__device__ __forceinline__ float wsum(float v) {
    #pragma unroll
    for (int o = 16; o > 0; o >>= 1) v += __shfl_xor_sync(0xffffffffu, v, o);
    return v;
}

__device__ __forceinline__ uint32_t s2u(const void* p) {
    uint32_t a;
    asm("{ .reg .u64 t; cvta.to.shared.u64 t, %1; cvt.u32.u64 %0, t; }"
        : "=r"(a) : "l"(p));
    return a;
}

__device__ __forceinline__ void cpasync16(uint32_t dst, const void* src) {
    asm volatile("cp.async.cg.shared.global [%0], [%1], 16;" :: "r"(dst), "l"(src));
}
__device__ __forceinline__ void cp_commit() { asm volatile("cp.async.commit_group;"); }
__device__ __forceinline__ void cp_wait0()  { asm volatile("cp.async.wait_group 0;" ::: "memory"); }
__device__ __forceinline__ void cp_wait1()  { asm volatile("cp.async.wait_group 1;" ::: "memory"); }

__device__ __forceinline__ void mbar_init(uint32_t a, uint32_t cnt) {
    asm volatile("mbarrier.init.shared.b64 [%0], %1;" :: "r"(a), "r"(cnt) : "memory");
}
__device__ __forceinline__ void mbar_wait(uint32_t a, uint32_t parity) {
    asm volatile(
        "{\n\t.reg .pred P;\n"
        "W%=:\n\t"
        "mbarrier.try_wait.parity.acquire.cta.shared::cta.b64 P, [%0], %1;\n\t"
        "@!P bra W%=;\n\t}"
        :: "r"(a), "r"(parity) : "memory");
}

#if TC_OK
__device__ __forceinline__ void tm_alloc(uint32_t smem_res, uint32_t ncols) {
    asm volatile("tcgen05.alloc.cta_group::1.sync.aligned.shared::cta.b32 [%0], %1;"
                 :: "r"(smem_res), "r"(ncols) : "memory");
}
__device__ __forceinline__ void tm_dealloc(uint32_t tmem, uint32_t ncols) {
    asm volatile("tcgen05.dealloc.cta_group::1.sync.aligned.b32 %0, %1;" :: "r"(tmem), "r"(ncols));
}
__device__ __forceinline__ void tm_commit(uint32_t mbar) {
    asm volatile("tcgen05.commit.cta_group::1.mbarrier::arrive::one.shared::cluster.b64 [%0];"
                 :: "r"(mbar) : "memory");
}
__device__ __forceinline__ void tm_fence_after() {
    asm volatile("tcgen05.fence::after_thread_sync;" ::: "memory");
}
__device__ __forceinline__ void fence_async_shared() {
    asm volatile("fence.proxy.async.shared::cta;" ::: "memory");
}
__device__ __forceinline__ void tm_waitld() {
    asm volatile("tcgen05.wait::ld.sync.aligned;" ::: "memory");
}
__device__ __forceinline__ void ldtm16(uint32_t* r, uint32_t a) {
    asm volatile("tcgen05.ld.sync.aligned.32x32b.x16.b32 "
                 "{%0,%1,%2,%3,%4,%5,%6,%7,%8,%9,%10,%11,%12,%13,%14,%15}, [%16];"
                 : "=r"(r[0]), "=r"(r[1]), "=r"(r[2]),  "=r"(r[3]),
                   "=r"(r[4]), "=r"(r[5]), "=r"(r[6]),  "=r"(r[7]),
                   "=r"(r[8]), "=r"(r[9]), "=r"(r[10]), "=r"(r[11]),
                   "=r"(r[12]), "=r"(r[13]), "=r"(r[14]), "=r"(r[15])
                 : "r"(a));
}

// SS bf16 MMA, cg1, fp32 accumulate.
#define IDESC_BF16_128x128 ((1u<<4)|(1u<<7)|(1u<<10)|((128u/8u)<<17)|((128u/16u)<<24))

__device__ __forceinline__ void mma_ss(uint32_t d, uint64_t a, uint64_t b,
                                       uint32_t en) {
    asm volatile(
        "{\n\t.reg .pred p;\n\t"
        "setp.ne.u32 p, %5, 0;\n\t"
        "tcgen05.mma.cta_group::1.kind::f16 [%0], %1, %2, %3, {%4, %4, %4, %4}, p;\n\t}"
        :: "r"(d), "l"(a), "l"(b), "r"(IDESC_BF16_128x128), "r"(0u), "r"(en)
        : "memory");
}
#endif  // TC_OK

// 64-bit SMEM descriptor: SW128, version 1 (Blackwell), SBO=64, LBO=1
__device__ __forceinline__ uint64_t mkdesc(uint32_t addr) {
    return ((uint64_t)2 << 61) | ((uint64_t)1 << 46) | ((uint64_t)64 << 32)
         | ((uint64_t)1 << 16) | (uint64_t)((addr >> 4) & 0x3FFFu);
}

// Atom-blocked SW128 offset for a 128-row x 128-col bf16 tile.
__device__ __forceinline__ uint32_t tile_off(int r, int g) {
    uint32_t lin = (uint32_t)((r >> 3) + ((g >> 3) << 4)) * 1024u
                 + (uint32_t)(r & 7) * 128u + (uint32_t)(g & 7) * 16u;
    return lin ^ ((lin >> 3) & 0x70u);
}

// -------------------- kernel 1: transpose W --------------------------------
__global__ void hd_transpose_W(const float* __restrict__ W) {
    int idx = blockIdx.x * blockDim.x + threadIdx.x;
    if (idx < DD * DD) {
        int d = idx >> 7, e = idx & (DD - 1);
        g_Wt[e * DD + d] = W[idx];
    }
}

// -------------------- kernel 2: per-code stats + bf16 split -----------------
__global__ void hd_prep_codes(const float* __restrict__ Y,
                              const float* __restrict__ fb, int K) {
    int lane = threadIdx.x & 31;
    int k = blockIdx.x * (blockDim.x >> 5) + (threadIdx.x >> 5);
    if (k >= K) return;
    const float* y = Y + (size_t)k * DD;
    float s = 0.f;
    #pragma unroll
    for (int q = 0; q < 4; q++) {
        int d = lane + 32 * q;
        float t = y[d];
        s = fmaf(t, t, s);
        __nv_bfloat16 hi = __float2bfloat16_rn(t);
        __nv_bfloat16 lo = __float2bfloat16_rn(t - __bfloat162float(hi));
        g_yhi[(size_t)k * DD + d] = hi;
        g_ylo[(size_t)k * DD + d] = lo;
    }
    s = wsum(s);
    if (lane == 0) {
        float ry = 1.f / fmaxf(1.f - s, 1e-12f);
        g_cc[k] = make_float4(s, ry, fb[k], 0.f);
    }
}

// -------------------- kernel 3: hyperbolic MLP, warp-per-row ----------------
__global__ void hd_prep_rows(const float* __restrict__ V,
                             const float* __restrict__ bvec, int N) {
    int lane = threadIdx.x & 31;
    int row = blockIdx.x * (blockDim.x >> 5) + (threadIdx.x >> 5);
    if (row >= N) return;
    const float* v = V + (size_t)row * DD;

    float vq[4];
    #pragma unroll
    for (int q = 0; q < 4; q++) vq[q] = v[lane + 32 * q];
    float n2 = wsum(vq[0]*vq[0] + vq[1]*vq[1] + vq[2]*vq[2] + vq[3]*vq[3]);
    float n  = sqrtf(fmaxf(n2, 1e-30f));
    float xn = tanhf(n);
    float s0 = xn / n;
    float p0[4];
    #pragma unroll
    for (int q = 0; q < 4; q++) p0[q] = s0 * vq[q];

    float mq[4] = {0.f, 0.f, 0.f, 0.f};
    #pragma unroll
    for (int e = 0; e < DD; e++) {
        float pe = __shfl_sync(0xffffffffu, p0[e >> 5], e & 31);
        #pragma unroll
        for (int q = 0; q < 4; q++)
            mq[q] = fmaf(pe, g_Wt[e * DD + 32 * q + lane], mq[q]);
    }
    float mxn2 = wsum(mq[0]*mq[0] + mq[1]*mq[1] + mq[2]*mq[2] + mq[3]*mq[3]);
    float mxn  = sqrtf(fmaxf(mxn2, 1e-30f));
    float xc   = fminf(xn, 1.f - 1e-5f);
    float ath  = 0.5f * __logf((1.f + xc) / (1.f - xc));
    float g    = tanhf(mxn / fmaxf(xn, 1e-15f) * ath) / mxn;
    float rq[4];
    #pragma unroll
    for (int q = 0; q < 4; q++) rq[q] = g * mq[q];

    float bq[4];
    #pragma unroll
    for (int q = 0; q < 4; q++) bq[q] = bvec[lane + 32 * q];
    float bn2 = wsum(bq[0]*bq[0] + bq[1]*bq[1] + bq[2]*bq[2] + bq[3]*bq[3]);
    float bn  = sqrtf(fmaxf(bn2, 1e-30f));
    float tb  = tanhf(bn);
    float sb  = tb / bn;
    float ebq[4];
    #pragma unroll
    for (int q = 0; q < 4; q++) ebq[q] = sb * bq[q];
    float y2 = tb * tb;

    float x2 = wsum(rq[0]*rq[0] + rq[1]*rq[1] + rq[2]*rq[2] + rq[3]*rq[3]);
    float xy = wsum(rq[0]*ebq[0] + rq[1]*ebq[1] + rq[2]*ebq[2] + rq[3]*ebq[3]);
    float ca  = 1.f + 2.f * xy + y2;
    float cb  = 1.f - x2;
    float den = fmaxf(1.f + 2.f * xy + x2 * y2, 1e-15f);
    float inv = 1.f / den;
    float pq[4], ps = 0.f;
    #pragma unroll
    for (int q = 0; q < 4; q++) {
        pq[q] = (ca * rq[q] + cb * ebq[q]) * inv;
        ps = fmaf(pq[q], pq[q], ps);
    }
    float px2 = wsum(ps);
    #pragma unroll
    for (int q = 0; q < 4; q++) {
        int d = lane + 32 * q;
        __nv_bfloat16 hi = __float2bfloat16_rn(pq[q]);
        __nv_bfloat16 lo = __float2bfloat16_rn(pq[q] - __bfloat162float(hi));
        g_phi[(size_t)row * DD + d] = hi;
        g_plo[(size_t)row * DD + d] = lo;
    }
    if (lane == 0) {
        g_x2[row] = px2;
        g_rx[row] = 2.f / fmaxf(1.f - px2, 1e-12f);
    }
}

// -------------------- kernel 4: tcgen05 GEMM + fused epilogue ---------------
#define NTHREADS 512
#define SM_TMEMPTR 0
#define SM_MBAR    8
#define SM_A       1024
#define SM_B       (SM_A + 65536)
#define SM_STG     (SM_B + 131072)
#define SM_TOTAL   (SM_STG + 16 * 16 * 33 * 4)   // 231424 <= 232448

__device__ __forceinline__ void fill_tile(uint32_t dst_base,
                                          const __nv_bfloat16* __restrict__ hi,
                                          const __nv_bfloat16* __restrict__ lo,
                                          int row0, int tid) {
    #pragma unroll
    for (int k = 0; k < 8; k++) {
        int idx = tid + NTHREADS * k;             // 4096 chunks total
        int s = idx >> 11, f = idx & 2047;
        int r = f >> 4, g = f & 15;
        const __nv_bfloat16* src = (s ? lo : hi) + ((size_t)(row0 + r) * DD + g * 8);
        cpasync16(dst_base + (uint32_t)s * 32768u + tile_off(r, g), src);
    }
}

#if TC_OK
__device__ __forceinline__ void issue_tile(uint32_t sa, uint32_t sbuf, uint32_t d) {
    uint64_t ah = mkdesc(sa), al = mkdesc(sa + 32768u);
    uint64_t bh = mkdesc(sbuf), bl = mkdesc(sbuf + 32768u);
    #pragma unroll
    for (int kk = 0; kk < 8; kk++) {
        uint32_t off = (uint32_t)(kk >> 2) * 1024u + (uint32_t)(kk & 3) * 2u;
        mma_ss(d, ah + off, bh + off, kk > 0 ? 1u : 0u);
        mma_ss(d, ah + off, bl + off, 1u);
        mma_ss(d, al + off, bh + off, 1u);
    }
}
#endif

__device__ __forceinline__ float hd_logit(float xv, float x2r, float rxr,
                                          const float4& q, float nit2) {
    float u = fmaf(-2.f, xv, x2r + q.x);
    u = fmaxf(u, 0.f);
    float zm1 = u * (rxr * q.y);
    float a = fmaxf(fmaf(zm1, zm1, 2.f * zm1), 1e-30f);
    float wq = a * rsqrtf(a);
    float l = __logf(1.f + zm1 + wq);
    return fmaf(l * l, nit2, q.z);
}

#if TC_OK
// process one 16-col chunk: compute logits, transpose via smem, store
__device__ __forceinline__ void emit_chunk(const uint32_t* r, float* stgf,
                                           float x2r, float rxr, float nit2,
                                           int colbase, int orow0, int lane,
                                           float* __restrict__ out, int K) {
    float res[16];
    #pragma unroll
    for (int j = 0; j < 16; j++) {
        float4 q = __ldg(&g_cc[colbase + j]);
        res[j] = hd_logit(__uint_as_float(r[j]), x2r, rxr, q, nit2);
    }
    #pragma unroll
    for (int j = 0; j < 16; j++)
        stgf[j * 33 + lane] = res[j];
    __syncwarp();
    #pragma unroll
    for (int it = 0; it < 4; it++) {
        int rr = it * 8 + (lane >> 2);
        int cc = (lane & 3) << 2;
        float4 v;
        v.x = stgf[(cc + 0) * 33 + rr];
        v.y = stgf[(cc + 1) * 33 + rr];
        v.z = stgf[(cc + 2) * 33 + rr];
        v.w = stgf[(cc + 3) * 33 + rr];
        *(float4*)(out + (size_t)(orow0 + rr) * K + colbase + cc) = v;
    }
    __syncwarp();
}
#endif

__global__ void __launch_bounds__(NTHREADS, 1)
hd_gemm_tc(const float* __restrict__ temp,
           float* __restrict__ out, int NROW, int K) {
    extern __shared__ char smem[];
    uint32_t sb = s2u(smem);
    int tid = threadIdx.x, w = tid >> 5, lane = tid & 31;

    const int NT = K >> 7;
    const int total = (NROW >> 7) * NT;
    const int per = (total + gridDim.x - 1) / gridDim.x;
    int t = blockIdx.x * per;
    const int tend = min(total, t + per);

    const float T = __ldg(temp);
    const float nit2 = -1.f / (T * T);

#if TC_OK
    if (w == 0) tm_alloc(sb + SM_TMEMPTR, 256);
    if (tid == 0) mbar_init(sb + SM_MBAR, 1);
    __syncthreads();
    uint32_t tbase;
    asm volatile("ld.shared.b32 %0, [%1];" : "=r"(tbase) : "r"(sb + SM_TMEMPTR));

    float* stgf = (float*)(smem + SM_STG) + w * (16 * 33);
    const int cq = w >> 2;                         // col quarter 0..3
    uint32_t ph = 0;
    while (t < tend) {
        const int m = t / NT;
        const int segend = min(tend, (m + 1) * NT);

        fill_tile(sb + SM_A, g_phi, g_plo, m << 7, tid);
        fill_tile(sb + SM_B + (uint32_t)(t & 1) * 65536u, g_yhi, g_ylo,
                  (t % NT) << 7, tid);
        cp_commit();
        if (t + 1 < segend) {
            fill_tile(sb + SM_B + (uint32_t)((t + 1) & 1) * 65536u, g_yhi, g_ylo,
                      ((t + 1) % NT) << 7, tid);
            cp_commit();
            cp_wait1();
        } else {
            cp_wait0();
        }
        __syncthreads();
        if (tid == 0) {
            fence_async_shared();
            issue_tile(sb + SM_A, sb + SM_B + (uint32_t)(t & 1) * 65536u,
                       tbase + (uint32_t)(t & 1) * 128u);
            tm_commit(sb + SM_MBAR);
        }

        const int orow0 = (m << 7) + ((w & 3) << 5);
        const int grow = orow0 + lane;
        const float x2r = g_x2[grow], rxr = g_rx[grow];

        for (int i = t; i < segend; i++) {
            mbar_wait(sb + SM_MBAR, ph);
            ph ^= 1;
            if (i + 1 < segend) {
                cp_wait0();
                __syncthreads();
                if (tid == 0) {
                    fence_async_shared();
                    issue_tile(sb + SM_A,
                               sb + SM_B + (uint32_t)((i + 1) & 1) * 65536u,
                               tbase + (uint32_t)((i + 1) & 1) * 128u);
                    tm_commit(sb + SM_MBAR);
                }
                if (i + 2 < segend) {
                    fill_tile(sb + SM_B + (uint32_t)(i & 1) * 65536u,
                              g_yhi, g_ylo, ((i + 2) % NT) << 7, tid);
                    cp_commit();
                }
            }
            tm_fence_after();
            const uint32_t dbase = tbase + (uint32_t)(i & 1) * 128u
                                 + (uint32_t)(cq << 5);
            const int colb = ((i % NT) << 7) + (cq << 5);
            uint32_t r0[16], r1[16];
            ldtm16(r0, dbase);
            ldtm16(r1, dbase + 16u);
            tm_waitld();
            emit_chunk(r0, stgf, x2r, rxr, nit2, colb,      orow0, lane, out, K);
            emit_chunk(r1, stgf, x2r, rxr, nit2, colb + 16, orow0, lane, out, K);
        }
        t = segend;
    }
    __syncthreads();
    if (w == 0) tm_dealloc(tbase, 256);
#else
    // -------- fallback (plain sm_103 cubin; GB300 loads the sm_103a one) ----
    float* Af = (float*)(smem);            // Af[d][m]
    float* Bf = (float*)(smem + 65536);    // Bf[d][n]
    const int tn = tid & 15, tm = (tid >> 4) & 15;
    const bool active = tid < 256;
    int cur_m = -1;
    while (t < tend) {
        const int m = t / NT, n = t % NT;
        __syncthreads();
        if (m != cur_m) {
            for (int idx = tid; idx < 128 * 128; idx += NTHREADS) {
                int r = idx >> 7, d = idx & 127;
                size_t o = (size_t)((m << 7) + r) * DD + d;
                Af[d * 128 + r] = __bfloat162float(g_phi[o]) + __bfloat162float(g_plo[o]);
            }
            cur_m = m;
        }
        for (int idx = tid; idx < 128 * 128; idx += NTHREADS) {
            int r = idx >> 7, d = idx & 127;
            size_t o = (size_t)((n << 7) + r) * DD + d;
            Bf[d * 128 + r] = __bfloat162float(g_yhi[o]) + __bfloat162float(g_ylo[o]);
        }
        __syncthreads();
        if (active) {
            float acc[8][8];
            #pragma unroll
            for (int i = 0; i < 8; i++)
                #pragma unroll
                for (int j = 0; j < 8; j++) acc[i][j] = 0.f;
            for (int d = 0; d < 128; d++) {
                float av[8], bv[8];
                #pragma unroll
                for (int i = 0; i < 8; i++) av[i] = Af[d * 128 + tm * 8 + i];
                #pragma unroll
                for (int j = 0; j < 8; j++) bv[j] = Bf[d * 128 + tn * 8 + j];
                #pragma unroll
                for (int i = 0; i < 8; i++)
                    #pragma unroll
                    for (int j = 0; j < 8; j++) acc[i][j] = fmaf(av[i], bv[j], acc[i][j]);
            }
            #pragma unroll
            for (int i = 0; i < 8; i++) {
                int grow = (m << 7) + tm * 8 + i;
                float x2r = g_x2[grow], rxr = g_rx[grow];
                #pragma unroll
                for (int j = 0; j < 8; j++) {
                    int c = (n << 7) + tn * 8 + j;
                    out[(size_t)grow * K + c] =
                        hd_logit(acc[i][j], x2r, rxr, g_cc[c], nit2);
                }
            }
        }
        t++;
    }
#endif
}

// -------------------- launch -------------------------------------------------
extern "C" void kernel_launch(void* const* d_in, const int* in_sizes, int n_in,
                              void* d_out, int out_size) {
    const float* v     = (const float*)d_in[0];
    const float* codes = (const float*)d_in[1];
    const float* W     = (const float*)d_in[2];
    const float* b     = (const float*)d_in[3];
    const float* fb    = (const float*)d_in[4];
    const float* temp  = (const float*)d_in[5];

    const int D = in_sizes[3];            // 128
    const int N = in_sizes[0] / D;        // 2048
    const int K = in_sizes[4];            // 32000

    cudaFuncSetAttribute(hd_gemm_tc, cudaFuncAttributeMaxDynamicSharedMemorySize,
                         SM_TOTAL);

    hd_transpose_W<<<(D * D + 255) / 256, 256>>>(W);
    hd_prep_codes<<<(K + 7) / 8, 256>>>(codes, fb, K);
    hd_prep_rows<<<(N + 7) / 8, 256>>>(v, b, N);
    hd_gemm_tc<<<148, NTHREADS, SM_TOTAL>>>(temp, (float*)d_out, N, K);
}